// round 7
// baseline (speedup 1.0000x reference)
#include <cuda_runtime.h>
#include <cuda_fp16.h>
#include <cstdint>

// ---------------------------------------------------------------------------
// out = relu(x·W1effᵀ + b1)·fc2ᵀ + b2   via mma.sync m16n8k16 (fp16 in, fp32 acc)
// 512-thread CTA, N-split across warp halves, 2 CTA/SM (32 warps).
// Padded-stride smem (144B rows) -> additive LDSM addresses, conflict-free.
// GEMM: M=65536 (128/CTA), N=104 (13 n-tiles), K=784 pad 832 (13 chunks x 64)
// ---------------------------------------------------------------------------

#define KPAD    832
#define NCHUNK  13
#define SROW    144                    // smem row stride, bytes
#define TILE_B  (128 * SROW)           // 18432 B per tile buffer

__device__ __half g_w1[128 * KPAD];

// ---------------- weight fold + fp16 conversion ----------------------------

__global__ void build_w1(const float* __restrict__ conv_w,
                         const float* __restrict__ fc1_w) {
    int idx = blockIdx.x * blockDim.x + threadIdx.x;
    if (idx >= 128 * KPAD) return;
    int n = idx / KPAD;
    int k = idx % KPAD;
    float v = 0.f;
    if (n < 100 && k < 784) {
        int y  = k / 28;
        int xx = k % 28;
        #pragma unroll
        for (int i = 0; i < 3; i++) {
            int r = y - i;
            if (r < 0 || r > 25) continue;
            #pragma unroll
            for (int j = 0; j < 3; j++) {
                int c = xx - j;
                if (c < 0 || c > 25) continue;
                v += fc1_w[n * 676 + r * 26 + c] * conv_w[i * 3 + j];
            }
        }
    }
    g_w1[n * KPAD + k] = __float2half(v);
}

// ---------------- PTX helpers ----------------------------------------------

__device__ __forceinline__ uint32_t smem_u32(const void* p) {
    uint32_t a;
    asm("{ .reg .u64 t; cvta.to.shared.u64 t, %1; cvt.u32.u64 %0, t; }"
        : "=r"(a) : "l"(p));
    return a;
}

__device__ __forceinline__ void ldsm_x4(uint32_t& r0, uint32_t& r1,
                                        uint32_t& r2, uint32_t& r3, uint32_t addr) {
    asm volatile("ldmatrix.sync.aligned.m8n8.x4.shared.b16 {%0,%1,%2,%3}, [%4];"
        : "=r"(r0), "=r"(r1), "=r"(r2), "=r"(r3) : "r"(addr));
}

__device__ __forceinline__ void ldsm_x2(uint32_t& r0, uint32_t& r1, uint32_t addr) {
    asm volatile("ldmatrix.sync.aligned.m8n8.x2.shared.b16 {%0,%1}, [%2];"
        : "=r"(r0), "=r"(r1) : "r"(addr));
}

__device__ __forceinline__ void mma16816(float* c,
                                         uint32_t a0, uint32_t a1, uint32_t a2, uint32_t a3,
                                         uint32_t b0, uint32_t b1) {
    asm volatile(
        "mma.sync.aligned.m16n8k16.row.col.f32.f16.f16.f32 "
        "{%0,%1,%2,%3}, {%4,%5,%6,%7}, {%8,%9}, {%0,%1,%2,%3};"
        : "+f"(c[0]), "+f"(c[1]), "+f"(c[2]), "+f"(c[3])
        : "r"(a0), "r"(a1), "r"(a2), "r"(a3), "r"(b0), "r"(b1));
}

// ---------------- staging helpers ------------------------------------------

// B tile: g_w1[n][ch*64 .. +63] -> smem rows (144B stride), via cp.async.
// 1024 16B copies, 2 per thread (512 threads).
__device__ __forceinline__ void stage_b_async(uint32_t bbuf, int ch, int tid) {
    #pragma unroll
    for (int i = 0; i < 2; i++) {
        int idx = tid + i * 512;
        int n  = idx >> 3;
        int k8 = idx & 7;
        uint32_t dst = bbuf + n * SROW + k8 * 16;
        const __half* s = &g_w1[n * KPAD + ch * 64 + k8 * 8];
        asm volatile("cp.async.cg.shared.global [%0], [%1], 16;"
                     :: "r"(dst), "l"(s) : "memory");
    }
    asm volatile("cp.async.commit_group;" ::: "memory");
}

// A prefetch: x fp32 -> fp16 pairs in registers. 2048 float4, 4/thread.
__device__ __forceinline__ void load_a_conv(const float* __restrict__ x, int m0,
                                            int Brows, int ch, int tid, uint2* av) {
    #pragma unroll
    for (int i = 0; i < 4; i++) {
        int idx = tid + i * 512;
        int m  = idx >> 4;
        int kq = idx & 15;
        int row = m0 + m;
        int kg  = ch * 64 + kq * 4;
        float4 v = make_float4(0.f, 0.f, 0.f, 0.f);
        if (row < Brows && kg < 784)
            v = *reinterpret_cast<const float4*>(&x[(size_t)row * 784 + kg]);
        __half2 h01 = __floats2half2_rn(v.x, v.y);
        __half2 h23 = __floats2half2_rn(v.z, v.w);
        av[i] = make_uint2(*reinterpret_cast<uint32_t*>(&h01),
                           *reinterpret_cast<uint32_t*>(&h23));
    }
}

__device__ __forceinline__ void store_a(uint32_t abuf, int tid, const uint2* av) {
    #pragma unroll
    for (int i = 0; i < 4; i++) {
        int idx = tid + i * 512;
        int m  = idx >> 4;
        int kq = idx & 15;
        uint32_t dst = abuf + m * SROW + kq * 8;
        asm volatile("st.shared.v2.b32 [%0], {%1,%2};"
                     :: "r"(dst), "r"(av[i].x), "r"(av[i].y) : "memory");
    }
}

// ---------------- fused GEMM + epilogue ------------------------------------

__global__ __launch_bounds__(512, 2)
void fused_gemm(const float* __restrict__ x,
                const float* __restrict__ fc1_b,
                const float* __restrict__ fc2_w,
                const float* __restrict__ fc2_b,
                float* __restrict__ out, int Brows) {
    extern __shared__ __align__(128) uint8_t dynsmem[];
    __shared__ float b1s[128];
    __shared__ float w2s[100][12];
    __shared__ float b2v[16];
    __shared__ float part[128][10];    // cross-half epilogue partials

    const int tid = threadIdx.x;
    const int wid = tid >> 5;
    const int lid = tid & 31;
    const int qid = lid & 3;
    const int qrow = lid >> 2;
    const int m0 = blockIdx.x * 128;
    const int half = wid >> 3;         // 0: n-tiles 0-6, 1: n-tiles 7-12
    const int mw = (wid & 7) * 16;     // warp's row base within tile

    const uint32_t sbase = smem_u32(dynsmem);
    const uint32_t aB[2] = { sbase, sbase + TILE_B };
    const uint32_t bB[2] = { sbase + 2 * TILE_B, sbase + 3 * TILE_B };

    // ldmatrix lane geometry (additive addresses)
    const int a_m  = mw + (lid & 15);
    const uint32_t a_off = (uint32_t)(a_m * SROW + (lid >> 4) * 16);
    const int b_nl = ((lid >> 4) & 1) * 8 + (lid & 7);
    const int b_ko = (lid >> 3) & 1;
    // per-half B lane row bases (pairs of tiles, 16 n each)
    const int nb0 = half ? (56 + b_nl) : b_nl;           // pair 0
    const uint32_t b_off0 = (uint32_t)(nb0 * SROW + b_ko * 16);
    const uint32_t b_off1 = b_off0 + 16 * SROW;
    const uint32_t b_off2 = b_off0 + 32 * SROW;
    // half0 extra x2 tile (tile 6, n=48..55)
    const uint32_t bx_off = (uint32_t)((48 + (lid & 7)) * SROW + b_ko * 16);

    if (tid < 128) b1s[tid] = (tid < 100) ? fc1_b[tid] : 0.f;
    if (tid < 100) {
        #pragma unroll
        for (int j = 0; j < 10; j++) w2s[tid][j] = fc2_w[j * 100 + tid];
    }
    if (tid < 10) b2v[tid] = fc2_b[tid];

    float c[7][4];
    #pragma unroll
    for (int t = 0; t < 7; t++)
        #pragma unroll
        for (int q = 0; q < 4; q++) c[t][q] = 0.f;

    uint2 av[4];

    // ---- prologue: stage chunk 0
    stage_b_async(bB[0], 0, tid);
    load_a_conv(x, m0, Brows, 0, tid, av);
    store_a(aB[0], tid, av);
    asm volatile("cp.async.wait_group 0;" ::: "memory");
    __syncthreads();

    // ---- pipelined mainloop
    for (int ch = 0; ch < NCHUNK; ch++) {
        const int cur = ch & 1;

        if (ch + 1 < NCHUNK) {
            stage_b_async(bB[cur ^ 1], ch + 1, tid);
            load_a_conv(x, m0, Brows, ch + 1, tid, av);
        }

        const uint32_t abase = aB[cur] + a_off;
        const uint32_t bbase = bB[cur];

        #pragma unroll
        for (int ks = 0; ks < 4; ks++) {
            uint32_t a0, a1, a2, a3;
            ldsm_x4(a0, a1, a2, a3, abase + ks * 32);
            uint32_t f0, f1, f2, f3;
            ldsm_x4(f0, f1, f2, f3, bbase + b_off0 + ks * 32);
            mma16816(c[0], a0, a1, a2, a3, f0, f1);
            mma16816(c[1], a0, a1, a2, a3, f2, f3);
            ldsm_x4(f0, f1, f2, f3, bbase + b_off1 + ks * 32);
            mma16816(c[2], a0, a1, a2, a3, f0, f1);
            mma16816(c[3], a0, a1, a2, a3, f2, f3);
            ldsm_x4(f0, f1, f2, f3, bbase + b_off2 + ks * 32);
            mma16816(c[4], a0, a1, a2, a3, f0, f1);
            mma16816(c[5], a0, a1, a2, a3, f2, f3);
            if (half == 0) {
                uint32_t g0, g1;
                ldsm_x2(g0, g1, bbase + bx_off + ks * 32);
                mma16816(c[6], a0, a1, a2, a3, g0, g1);
            }
        }

        if (ch + 1 < NCHUNK) {
            store_a(aB[cur ^ 1], tid, av);
            asm volatile("cp.async.wait_group 0;" ::: "memory");
        }
        __syncthreads();
    }

    // ---- epilogue: h = relu(c + b1); p = h·fc2ᵀ; quad-reduce; combine halves
    const int ntiles = half ? 6 : 7;
    const int nbase  = half ? 56 : 0;

    float p0[10], p1[10];
    #pragma unroll
    for (int j = 0; j < 10; j++) { p0[j] = 0.f; p1[j] = 0.f; }

    #pragma unroll
    for (int t = 0; t < 7; t++) {
        if (t >= ntiles) break;
        #pragma unroll
        for (int e = 0; e < 2; e++) {
            int n = nbase + t * 8 + qid * 2 + e;
            if (n < 100) {
                float h0 = fmaxf(c[t][0 + e] + b1s[n], 0.f);  // row qrow
                float h1 = fmaxf(c[t][2 + e] + b1s[n], 0.f);  // row qrow+8
                #pragma unroll
                for (int j = 0; j < 10; j++) {
                    p0[j] = fmaf(h0, w2s[n][j], p0[j]);
                    p1[j] = fmaf(h1, w2s[n][j], p1[j]);
                }
            }
        }
    }
    #pragma unroll
    for (int mask = 2; mask >= 1; mask >>= 1) {
        #pragma unroll
        for (int j = 0; j < 10; j++) {
            p0[j] += __shfl_xor_sync(0xffffffffu, p0[j], mask);
            p1[j] += __shfl_xor_sync(0xffffffffu, p1[j], mask);
        }
    }

    // half1 deposits partials; half0 combines + stores
    if (half == 1 && qid == 0) {
        int r0 = mw + qrow;
        #pragma unroll
        for (int j = 0; j < 10; j++) {
            part[r0][j]     = p0[j];
            part[r0 + 8][j] = p1[j];
        }
    }
    __syncthreads();
    if (half == 0 && qid == 0) {
        int r0 = mw + qrow;
        int row0 = m0 + r0;
        int row1 = row0 + 8;
        if (row0 < Brows) {
            #pragma unroll
            for (int j = 0; j < 10; j++)
                out[(size_t)row0 * 10 + j] = p0[j] + part[r0][j] + b2v[j];
        }
        if (row1 < Brows) {
            #pragma unroll
            for (int j = 0; j < 10; j++)
                out[(size_t)row1 * 10 + j] = p1[j] + part[r0 + 8][j] + b2v[j];
        }
    }
}

// ---------------- launch ---------------------------------------------------

extern "C" void kernel_launch(void* const* d_in, const int* in_sizes, int n_in,
                              void* d_out, int out_size) {
    const float* x      = (const float*)d_in[0];
    const float* conv_w = (const float*)d_in[1];
    const float* fc1_w  = (const float*)d_in[2];
    const float* fc1_b  = (const float*)d_in[3];
    const float* fc2_w  = (const float*)d_in[4];
    const float* fc2_b  = (const float*)d_in[5];
    float* out = (float*)d_out;

    int Brows = in_sizes[0] / 784;

    build_w1<<<(128 * KPAD + 255) / 256, 256>>>(conv_w, fc1_w);

    const int smem_bytes = 4 * TILE_B;  // 72 KB
    cudaFuncSetAttribute(fused_gemm, cudaFuncAttributeMaxDynamicSharedMemorySize,
                         smem_bytes);

    int grid = (Brows + 127) / 128;
    fused_gemm<<<grid, 512, smem_bytes>>>(x, fc1_b, fc2_w, fc2_b, out, Brows);
}

// round 8
// speedup vs baseline: 1.3096x; 1.3096x over previous
#include <cuda_runtime.h>
#include <cuda_fp16.h>
#include <cstdint>

// ---------------------------------------------------------------------------
// out = relu(x·W1effᵀ + b1)·fc2ᵀ + b2   via mma.sync m16n8k16 (fp16 in, fp32 acc)
// B (folded conv+fc1 weights, 104x784 fp16 = 163KB) resident in smem for the
// whole kernel; A fragments LDG'd straight from gmem into mma layout (no smem).
// Barrier-free mainloop over 49 k16-steps, A prefetched 3 steps ahead.
// CTA: 512 thr, 16 warps x 16 rows = 256 rows. Grid 256, 1 CTA/SM.
// ---------------------------------------------------------------------------

#define KW      784
#define NSTEP   49                 // 784 / 16 exactly
#define BSTRIDE 3328               // 104 n-rows * 32 B per k-step
#define BSMEM   (NSTEP * BSTRIDE)  // 163072 B

__device__ __half g_w1[104 * KW];

// ---------------- weight fold + fp16 conversion ----------------------------

__global__ void build_w1(const float* __restrict__ conv_w,
                         const float* __restrict__ fc1_w) {
    int idx = blockIdx.x * blockDim.x + threadIdx.x;
    if (idx >= 104 * KW) return;
    int n = idx / KW;
    int k = idx % KW;
    float v = 0.f;
    if (n < 100) {
        int y  = k / 28;
        int xx = k % 28;
        #pragma unroll
        for (int i = 0; i < 3; i++) {
            int r = y - i;
            if (r < 0 || r > 25) continue;
            #pragma unroll
            for (int j = 0; j < 3; j++) {
                int c = xx - j;
                if (c < 0 || c > 25) continue;
                v += fc1_w[n * 676 + r * 26 + c] * conv_w[i * 3 + j];
            }
        }
    }
    g_w1[n * KW + k] = __float2half(v);
}

// ---------------- PTX helpers ----------------------------------------------

__device__ __forceinline__ uint32_t smem_u32(const void* p) {
    uint32_t a;
    asm("{ .reg .u64 t; cvta.to.shared.u64 t, %1; cvt.u32.u64 %0, t; }"
        : "=r"(a) : "l"(p));
    return a;
}

__device__ __forceinline__ void ldsm_x4(uint32_t& r0, uint32_t& r1,
                                        uint32_t& r2, uint32_t& r3, uint32_t addr) {
    asm volatile("ldmatrix.sync.aligned.m8n8.x4.shared.b16 {%0,%1,%2,%3}, [%4];"
        : "=r"(r0), "=r"(r1), "=r"(r2), "=r"(r3) : "r"(addr));
}

__device__ __forceinline__ void ldsm_x2(uint32_t& r0, uint32_t& r1, uint32_t addr) {
    asm volatile("ldmatrix.sync.aligned.m8n8.x2.shared.b16 {%0,%1}, [%2];"
        : "=r"(r0), "=r"(r1) : "r"(addr));
}

__device__ __forceinline__ void mma16816(float* c,
                                         uint32_t a0, uint32_t a1, uint32_t a2, uint32_t a3,
                                         uint32_t b0, uint32_t b1) {
    asm volatile(
        "mma.sync.aligned.m16n8k16.row.col.f32.f16.f16.f32 "
        "{%0,%1,%2,%3}, {%4,%5,%6,%7}, {%8,%9}, {%0,%1,%2,%3};"
        : "+f"(c[0]), "+f"(c[1]), "+f"(c[2]), "+f"(c[3])
        : "r"(a0), "r"(a1), "r"(a2), "r"(a3), "r"(b0), "r"(b1));
}

// ---------------- fused GEMM + epilogue ------------------------------------

__global__ __launch_bounds__(512, 1)
void fused_gemm(const float* __restrict__ x,
                const float* __restrict__ fc1_b,
                const float* __restrict__ fc2_w,
                const float* __restrict__ fc2_b,
                float* __restrict__ out, int Brows) {
    extern __shared__ __align__(128) uint8_t dynsmem[];   // B: 163072 B
    __shared__ float b1s[128];
    __shared__ float w2s[100][12];
    __shared__ float b2v[16];

    const int tid = threadIdx.x;
    const int wid = tid >> 5;
    const int lid = tid & 31;
    const int qid = lid & 3;
    const int qrow = lid >> 2;           // 0..7 (= g)
    const int m0 = blockIdx.x * 256;
    const int mw = wid * 16;

    const uint32_t bbase = smem_u32(dynsmem);

    // ---- stage B once: g_w1[n][k] -> [step s][n][16 k], swizzled 16B chunks
    for (int idx = tid; idx < NSTEP * 104 * 2; idx += 512) {
        int c = idx & 1;
        int n = (idx >> 1) % 104;
        int s = (idx >> 1) / 104;
        uint32_t dst = bbase + (uint32_t)(s * 104 + n) * 32
                     + ((c ^ ((n >> 2) & 1)) << 4);
        const __half* src = &g_w1[n * KW + s * 16 + c * 8];
        asm volatile("cp.async.cg.shared.global [%0], [%1], 16;"
                     :: "r"(dst), "l"(src) : "memory");
    }
    asm volatile("cp.async.commit_group;" ::: "memory");

    if (tid < 128) b1s[tid] = (tid < 100) ? fc1_b[tid] : 0.f;
    if (tid < 100) {
        #pragma unroll
        for (int j = 0; j < 10; j++) w2s[tid][j] = fc2_w[j * 100 + tid];
    }
    if (tid < 10) b2v[tid] = fc2_b[tid];

    // ---- B ldmatrix lane offsets (constant per thread, additive per step)
    const int b_nl = ((lid >> 4) & 1) * 8 + (lid & 7);
    const int b_ko = (lid >> 3) & 1;
    uint32_t boff[6];
    #pragma unroll
    for (int tp = 0; tp < 6; tp++) {
        int n_l = tp * 16 + b_nl;
        boff[tp] = (uint32_t)(n_l * 32 + ((b_ko ^ ((n_l >> 2) & 1)) << 4));
    }
    const int nx = 96 + (lid & 7);
    const uint32_t bxoff = (uint32_t)(nx * 32 + ((b_ko ^ ((nx >> 2) & 1)) << 4));

    // ---- A direct-LDG geometry: rows g, g+8; k = (lid&3)*2, +8
    const int r0 = m0 + mw + qrow;
    const int r1 = r0 + 8;
    const bool v0 = r0 < Brows;
    const bool v1 = r1 < Brows;
    const float* xp0 = x + (size_t)r0 * KW + qid * 2;
    const float* xp1 = x + (size_t)r1 * KW + qid * 2;

    float c[13][4];
    #pragma unroll
    for (int t = 0; t < 13; t++)
        #pragma unroll
        for (int q = 0; q < 4; q++) c[t][q] = 0.f;

    // prefetch buffers: [4] = {row g k-lo, row g k-hi, row g+8 k-lo, row g+8 k-hi}
    float2 pf0[4], pf1[4], pf2[4];

    #define LOAD_A(s, pf) do {                                                \
        const float2 z2 = make_float2(0.f, 0.f);                              \
        (pf)[0] = v0 ? *reinterpret_cast<const float2*>(xp0 + (s) * 16)      : z2; \
        (pf)[1] = v0 ? *reinterpret_cast<const float2*>(xp0 + (s) * 16 + 8)  : z2; \
        (pf)[2] = v1 ? *reinterpret_cast<const float2*>(xp1 + (s) * 16)      : z2; \
        (pf)[3] = v1 ? *reinterpret_cast<const float2*>(xp1 + (s) * 16 + 8)  : z2; \
    } while (0)

    #define STEP(s, pf) do {                                                  \
        __half2 ha0 = __floats2half2_rn((pf)[0].x, (pf)[0].y);                \
        __half2 ha2 = __floats2half2_rn((pf)[1].x, (pf)[1].y);                \
        __half2 ha1 = __floats2half2_rn((pf)[2].x, (pf)[2].y);                \
        __half2 ha3 = __floats2half2_rn((pf)[3].x, (pf)[3].y);                \
        uint32_t a0 = *reinterpret_cast<uint32_t*>(&ha0);                     \
        uint32_t a1 = *reinterpret_cast<uint32_t*>(&ha1);                     \
        uint32_t a2 = *reinterpret_cast<uint32_t*>(&ha2);                     \
        uint32_t a3 = *reinterpret_cast<uint32_t*>(&ha3);                     \
        uint32_t sb = bbase + (uint32_t)(s) * BSTRIDE;                        \
        uint32_t f0, f1, f2, f3;                                              \
        ldsm_x4(f0, f1, f2, f3, sb + boff[0]);                                \
        mma16816(c[0], a0, a1, a2, a3, f0, f1);                               \
        mma16816(c[1], a0, a1, a2, a3, f2, f3);                               \
        ldsm_x4(f0, f1, f2, f3, sb + boff[1]);                                \
        mma16816(c[2], a0, a1, a2, a3, f0, f1);                               \
        mma16816(c[3], a0, a1, a2, a3, f2, f3);                               \
        ldsm_x4(f0, f1, f2, f3, sb + boff[2]);                                \
        mma16816(c[4], a0, a1, a2, a3, f0, f1);                               \
        mma16816(c[5], a0, a1, a2, a3, f2, f3);                               \
        ldsm_x4(f0, f1, f2, f3, sb + boff[3]);                                \
        mma16816(c[6], a0, a1, a2, a3, f0, f1);                               \
        mma16816(c[7], a0, a1, a2, a3, f2, f3);                               \
        ldsm_x4(f0, f1, f2, f3, sb + boff[4]);                                \
        mma16816(c[8], a0, a1, a2, a3, f0, f1);                               \
        mma16816(c[9], a0, a1, a2, a3, f2, f3);                               \
        ldsm_x4(f0, f1, f2, f3, sb + boff[5]);                                \
        mma16816(c[10], a0, a1, a2, a3, f0, f1);                              \
        mma16816(c[11], a0, a1, a2, a3, f2, f3);                              \
        ldsm_x2(f0, f1, sb + bxoff);                                          \
        mma16816(c[12], a0, a1, a2, a3, f0, f1);                              \
    } while (0)

    LOAD_A(0, pf0);
    LOAD_A(1, pf1);
    LOAD_A(2, pf2);

    // wait for B staging, then barrier-free mainloop
    asm volatile("cp.async.wait_group 0;" ::: "memory");
    __syncthreads();

    #pragma unroll 1
    for (int s = 0; s < 48; s += 3) {
        STEP(s, pf0);
        if (s + 3 < NSTEP) LOAD_A(s + 3, pf0);
        STEP(s + 1, pf1);
        if (s + 4 < NSTEP) LOAD_A(s + 4, pf1);
        STEP(s + 2, pf2);
        if (s + 5 < NSTEP) LOAD_A(s + 5, pf2);
    }
    STEP(48, pf0);

    // ---- epilogue: h = relu(c + b1); p = h·fc2ᵀ; quad-reduce; + b2; store
    float p0[10], p1[10];
    #pragma unroll
    for (int j = 0; j < 10; j++) { p0[j] = 0.f; p1[j] = 0.f; }

    #pragma unroll
    for (int t = 0; t < 13; t++) {
        #pragma unroll
        for (int e = 0; e < 2; e++) {
            int n = t * 8 + qid * 2 + e;
            if (n < 100) {
                float h0 = fmaxf(c[t][0 + e] + b1s[n], 0.f);  // row qrow
                float h1 = fmaxf(c[t][2 + e] + b1s[n], 0.f);  // row qrow+8
                #pragma unroll
                for (int j = 0; j < 10; j++) {
                    p0[j] = fmaf(h0, w2s[n][j], p0[j]);
                    p1[j] = fmaf(h1, w2s[n][j], p1[j]);
                }
            }
        }
    }
    #pragma unroll
    for (int mask = 2; mask >= 1; mask >>= 1) {
        #pragma unroll
        for (int j = 0; j < 10; j++) {
            p0[j] += __shfl_xor_sync(0xffffffffu, p0[j], mask);
            p1[j] += __shfl_xor_sync(0xffffffffu, p1[j], mask);
        }
    }
    if (qid == 0) {
        if (v0) {
            #pragma unroll
            for (int j = 0; j < 10; j++)
                out[(size_t)r0 * 10 + j] = p0[j] + b2v[j];
        }
        if (v1) {
            #pragma unroll
            for (int j = 0; j < 10; j++)
                out[(size_t)r1 * 10 + j] = p1[j] + b2v[j];
        }
    }
}

// ---------------- launch ---------------------------------------------------

extern "C" void kernel_launch(void* const* d_in, const int* in_sizes, int n_in,
                              void* d_out, int out_size) {
    const float* x      = (const float*)d_in[0];
    const float* conv_w = (const float*)d_in[1];
    const float* fc1_w  = (const float*)d_in[2];
    const float* fc1_b  = (const float*)d_in[3];
    const float* fc2_w  = (const float*)d_in[4];
    const float* fc2_b  = (const float*)d_in[5];
    float* out = (float*)d_out;

    int Brows = in_sizes[0] / KW;

    build_w1<<<(104 * KW + 255) / 256, 256>>>(conv_w, fc1_w);

    cudaFuncSetAttribute(fused_gemm, cudaFuncAttributeMaxDynamicSharedMemorySize,
                         BSMEM);

    int grid = (Brows + 255) / 256;
    fused_gemm<<<grid, 512, BSMEM>>>(x, fc1_b, fc2_w, fc2_b, out, Brows);
}